// round 1
// baseline (speedup 1.0000x reference)
#include <cuda_runtime.h>
#include <math.h>

#define H 256
#define INDIM 128
#define WDIM 512
#define RANKV 10
#define NMAX 50000
#define EMAX 800000
#define SLOPE 0.01f

// ---------------- device scratch (no runtime allocation allowed) ----------------
__device__ float g_agg [NMAX * H];
__device__ float g_buf1[NMAX * H];
__device__ float g_buf2[NMAX * H];
__device__ float g_styles[3][2 * H * RANKV];   // 5120 per synth
__device__ float g_WT [3][H * H];              // WT[syn][k*H + i] = W[i][k]  (B layout [K][N])
__device__ float g_C1 [H * H];                 // (I + cat1_w^T) as [k][i]
__device__ float g_E2 [H * H];                 // (I + cat2_w^T) as [m][i]
__device__ float g_NM2[INDIM * H];             // nm_w^T @ E2, [k][i]
__device__ float g_b2 [H];

// ---------------- styles = aw @ w + ab (3 synths, rows=5120, K=512) ----------------
__global__ void k_styles(const float* __restrict__ aw0, const float* __restrict__ ab0,
                         const float* __restrict__ aw1, const float* __restrict__ ab1,
                         const float* __restrict__ aw2, const float* __restrict__ ab2,
                         const float* __restrict__ w)
{
    int syn = blockIdx.y;
    const float* aw = (syn == 0) ? aw0 : (syn == 1) ? aw1 : aw2;
    const float* ab = (syn == 0) ? ab0 : (syn == 1) ? ab1 : ab2;
    int row  = blockIdx.x * 8 + (threadIdx.x >> 5);
    int lane = threadIdx.x & 31;
    if (row >= 2 * H * RANKV) return;
    const float* ar = aw + (size_t)row * WDIM;
    float s = 0.f;
    #pragma unroll 4
    for (int t = lane; t < WDIM; t += 32) s += ar[t] * w[t];
    #pragma unroll
    for (int o = 16; o; o >>= 1) s += __shfl_xor_sync(0xffffffffu, s, o);
    if (lane == 0) g_styles[syn][row] = s + ab[row];
}

// ---------------- modulated + row-normalized weight, stored transposed ----------------
__global__ void k_modweight(const float* __restrict__ w0,
                            const float* __restrict__ w1,
                            const float* __restrict__ w2)
{
    int syn = blockIdx.y;
    int i   = blockIdx.x;      // output row (c_out)
    int j   = threadIdx.x;     // input col (c_in), 256 threads
    const float* weight = (syn == 0) ? w0 : (syn == 1) ? w1 : w2;
    const float* st = g_styles[syn];
    __shared__ float L[RANKV];
    __shared__ float red[H];
    if (j < RANKV) L[j] = st[i * RANKV + j];
    __syncthreads();
    const float inv_sqrt_rank = 0.31622776601683794f;  // 1/sqrt(10)
    float mod = 0.f;
    #pragma unroll
    for (int r = 0; r < RANKV; r++) mod += L[r] * st[H * RANKV + r * H + j];
    float wv = weight[i * H + j] * (mod * inv_sqrt_rank + 1.0f);
    red[j] = wv * wv;
    __syncthreads();
    for (int o = 128; o; o >>= 1) { if (j < o) red[j] += red[j + o]; __syncthreads(); }
    float norm = sqrtf(red[0]) + 1e-8f;
    g_WT[syn][j * H + i] = wv / norm;  // transposed store: [K][N]
}

// ---------------- C1 = I + cat1^T ; E2 = I + cat2^T ----------------
__global__ void k_prep_ce(const float* __restrict__ cat1_w,
                          const float* __restrict__ cat2_w)
{
    int idx = blockIdx.x * blockDim.x + threadIdx.x;   // 65536
    int i = idx >> 8, k = idx & 255;
    float eye = (i == k) ? 1.f : 0.f;
    g_C1[k * H + i] = cat1_w[i * H + k] + eye;
    g_E2[k * H + i] = cat2_w[i * H + k] + eye;
}

// ---------------- NM2 = nm_w^T @ E2 ; b2 = nm_b @ E2 + cat2_b ----------------
__global__ void k_prep_nm(const float* __restrict__ nm_w,
                          const float* __restrict__ nm_b,
                          const float* __restrict__ cat2_b)
{
    int idx = blockIdx.x * blockDim.x + threadIdx.x;   // 32768
    if (idx >= INDIM * H) return;
    int i = idx & 255;   // output col
    int k = idx >> 8;    // 0..127
    float s = 0.f;
    #pragma unroll 4
    for (int m = 0; m < H; m++) s += nm_w[m * INDIM + k] * g_E2[m * H + i];
    g_NM2[k * H + i] = s;
    if (k == 0) {
        float b = cat2_b[i];
        for (int m = 0; m < H; m++) b += nm_b[m] * g_E2[m * H + i];
        g_b2[i] = b;
    }
}

// ---------------- agg init: agg[n][h] = edge_bias[h] ----------------
__global__ void k_agg_init(const float* __restrict__ edge_bias, int n)
{
    int idx = blockIdx.x * blockDim.x + threadIdx.x;   // float4 index
    if (idx >= n * (H / 4)) return;
    float4 eb = ((const float4*)edge_bias)[idx & 63];
    ((float4*)g_agg)[idx] = eb;
}

// ---------------- scatter-add: warp per edge, vector f32 reductions ----------------
__global__ void k_scatter(const int* __restrict__ ei,
                          const float* __restrict__ nw, int E)
{
    int e = blockIdx.x * 8 + (threadIdx.x >> 5);
    if (e >= E) return;
    int lane = threadIdx.x & 31;
    int s = ei[e];
    int d = ei[E + e];
    const float4* srcp = (const float4*)(nw + (size_t)s * H);
    float4*       dstp = (float4*)(g_agg + (size_t)d * H);
    #pragma unroll
    for (int t = 0; t < 2; t++) {
        int c = lane + t * 32;
        float4 v = srcp[c];
        asm volatile("red.global.add.v4.f32 [%0], {%1,%2,%3,%4};"
                     :: "l"((float*)(dstp + c)),
                        "f"(v.x), "f"(v.y), "f"(v.z), "f"(v.w)
                     : "memory");
    }
}

// ---------------- fp32 SIMT GEMM: C = epi(A[M,K] @ B[K,N] (+bias)(+C_old)) ----------------
#define BM 128
#define BN 128
#define BK 8
__global__ void __launch_bounds__(256) k_gemm(
    const float* __restrict__ A, const float* __restrict__ B,
    float* __restrict__ C, int M, int N, int K,
    const float* __restrict__ bias, int leaky, int acc)
{
    __shared__ float As[BK][BM];
    __shared__ float Bs[BK][BN];
    int tid = threadIdx.x;
    int tx = tid & 15, ty = tid >> 4;
    int mBase = blockIdx.x * BM;
    int nBase = blockIdx.y * BN;

    int aRow = tid >> 1;           // 0..127
    int aCol = (tid & 1) * 4;      // 0 or 4
    int bRow = tid >> 5;           // 0..7
    int bCol = (tid & 31) * 4;     // 0..124

    bool aValid = (mBase + aRow) < M;
    const float* Aptr = A + (size_t)(mBase + aRow) * K + aCol;
    const float* Bptr = B + (size_t)bRow * N + nBase + bCol;

    float accu[8][8] = {};
    float4 av = aValid ? *(const float4*)(Aptr) : make_float4(0, 0, 0, 0);
    float4 bv = *(const float4*)(Bptr);

    for (int k0 = 0; k0 < K; k0 += BK) {
        As[aCol + 0][aRow] = av.x;
        As[aCol + 1][aRow] = av.y;
        As[aCol + 2][aRow] = av.z;
        As[aCol + 3][aRow] = av.w;
        *(float4*)&Bs[bRow][bCol] = bv;
        __syncthreads();
        int kn = k0 + BK;
        if (kn < K) {  // prefetch next tile while computing
            av = aValid ? *(const float4*)(Aptr + kn) : make_float4(0, 0, 0, 0);
            bv = *(const float4*)(Bptr + (size_t)kn * N);
        }
        #pragma unroll
        for (int kk = 0; kk < BK; kk++) {
            float a[8], b[8];
            *(float4*)(a    ) = *(const float4*)&As[kk][ty * 8];
            *(float4*)(a + 4) = *(const float4*)&As[kk][ty * 8 + 4];
            *(float4*)(b    ) = *(const float4*)&Bs[kk][tx * 8];
            *(float4*)(b + 4) = *(const float4*)&Bs[kk][tx * 8 + 4];
            #pragma unroll
            for (int i = 0; i < 8; i++)
                #pragma unroll
                for (int j = 0; j < 8; j++)
                    accu[i][j] += a[i] * b[j];
        }
        __syncthreads();
    }

    float bvals[8];
    #pragma unroll
    for (int j = 0; j < 8; j++) bvals[j] = bias ? bias[nBase + tx * 8 + j] : 0.f;

    #pragma unroll
    for (int i = 0; i < 8; i++) {
        int row = mBase + ty * 8 + i;
        if (row < M) {
            float* Crow = C + (size_t)row * N + nBase + tx * 8;
            #pragma unroll
            for (int j4 = 0; j4 < 2; j4++) {
                float4 old = acc ? *(const float4*)(Crow + j4 * 4)
                                 : make_float4(0, 0, 0, 0);
                float ov[4] = {old.x, old.y, old.z, old.w};
                float4 o;
                float* op = &o.x;
                #pragma unroll
                for (int j = 0; j < 4; j++) {
                    float v = accu[i][j4 * 4 + j] + bvals[j4 * 4 + j] + ov[j];
                    if (leaky) v = (v >= 0.f) ? v : SLOPE * v;
                    op[j] = v;
                }
                *(float4*)(Crow + j4 * 4) = o;
            }
        }
    }
}

// ---------------- launch ----------------
extern "C" void kernel_launch(void* const* d_in, const int* in_sizes, int n_in,
                              void* d_out, int out_size)
{
    const float* x          = (const float*)d_in[0];
    const int*   edge_index = (const int*)  d_in[1];
    const float* w          = (const float*)d_in[2];
    const float* node_w     = (const float*)d_in[3];
    const float* edge_bias  = (const float*)d_in[4];
    const float* le_aw      = (const float*)d_in[5];
    const float* le_ab      = (const float*)d_in[6];
    const float* le_weight  = (const float*)d_in[7];
    const float* le_bias    = (const float*)d_in[8];
    // d_in[9] = le_ns (zero scalar; noise term vanishes)
    const float* cat1_w     = (const float*)d_in[10];
    const float* cat1_b     = (const float*)d_in[11];
    const float* cat2_w     = (const float*)d_in[12];
    const float* cat2_b     = (const float*)d_in[13];
    const float* nm_w       = (const float*)d_in[14];
    const float* nm_b       = (const float*)d_in[15];
    const float* f1_aw      = (const float*)d_in[16];
    const float* f1_ab      = (const float*)d_in[17];
    const float* f1_weight  = (const float*)d_in[18];
    const float* f1_bias    = (const float*)d_in[19];
    // d_in[20] = f1_ns
    const float* f2_aw      = (const float*)d_in[21];
    const float* f2_ab      = (const float*)d_in[22];
    const float* f2_weight  = (const float*)d_in[23];
    const float* f2_bias    = (const float*)d_in[24];
    // d_in[25] = f2_ns

    int N = in_sizes[3] / H;
    int E = in_sizes[1] / 2;

    float *agg, *b1, *b2, *wt, *c1, *nm2, *b2v;
    cudaGetSymbolAddress((void**)&agg, g_agg);
    cudaGetSymbolAddress((void**)&b1,  g_buf1);
    cudaGetSymbolAddress((void**)&b2,  g_buf2);
    cudaGetSymbolAddress((void**)&wt,  g_WT);
    cudaGetSymbolAddress((void**)&c1,  g_C1);
    cudaGetSymbolAddress((void**)&nm2, g_NM2);
    cudaGetSymbolAddress((void**)&b2v, g_b2);

    // weight prep (tiny)
    k_styles   <<<dim3(2 * H * RANKV / 8, 3), 256>>>(le_aw, le_ab, f1_aw, f1_ab, f2_aw, f2_ab, w);
    k_modweight<<<dim3(H, 3), 256>>>(le_weight, f1_weight, f2_weight);
    k_prep_ce  <<<H * H / 256, 256>>>(cat1_w, cat2_w);
    k_prep_nm  <<<INDIM * H / 256, 256>>>(nm_w, nm_b, cat2_b);

    // graph aggregation
    k_agg_init <<<(N * (H / 4) + 255) / 256, 256>>>(edge_bias, N);
    k_scatter  <<<(E + 7) / 8, 256>>>(edge_index, node_w, E);

    dim3 gg((N + BM - 1) / BM, H / BN);
    // out1 = leaky(agg @ W_le^T + le_bias)
    k_gemm<<<gg, 256>>>(agg, wt + 0 * H * H, b1, N, H, H, le_bias, 1, 0);
    // tmp  = out1 @ (I + cat1^T) + cat1_b
    k_gemm<<<gg, 256>>>(b1, c1, b2, N, H, H, cat1_b, 0, 0);
    // out4 = leaky(tmp + x @ NM2 + b2)
    k_gemm<<<gg, 256>>>(x, nm2, b2, N, H, INDIM, b2v, 1, 1);
    // out5 = leaky(out4 @ W_f1^T + f1_bias)
    k_gemm<<<gg, 256>>>(b2, wt + 1 * H * H, b1, N, H, H, f1_bias, 1, 0);
    // out  = leaky(out5 @ W_f2^T + f2_bias)
    k_gemm<<<gg, 256>>>(b1, wt + 2 * H * H, (float*)d_out, N, H, H, f2_bias, 1, 0);
}

// round 2
// speedup vs baseline: 1.2104x; 1.2104x over previous
#include <cuda_runtime.h>
#include <math.h>
#include <stdint.h>

#define H 256
#define INDIM 128
#define WDIM 512
#define RANKV 10
#define NMAX 50000
#define SLOPE 0.01f

// ---------------- device scratch ----------------
__device__ float g_agg [NMAX * H];
__device__ float g_buf1[NMAX * H];
__device__ float g_buf2[NMAX * H];
__device__ float g_styles[3][2 * H * RANKV];
__device__ float g_WT [3][H * H];      // [k][n] = W[n][k]
__device__ float g_C1 [H * H];         // (I + cat1^T) [k][n]
__device__ float g_E2 [H * H];         // (I + cat2^T) [m][n]
__device__ float g_NM2[INDIM * H];     // nm_w^T @ E2  [k][n]
__device__ float g_b2 [H];             // cat1_b + cat2_b + nm_b @ E2

// ---------------- styles = aw @ w + ab ----------------
__global__ void k_styles(const float* __restrict__ aw0, const float* __restrict__ ab0,
                         const float* __restrict__ aw1, const float* __restrict__ ab1,
                         const float* __restrict__ aw2, const float* __restrict__ ab2,
                         const float* __restrict__ w)
{
    int syn = blockIdx.y;
    const float* aw = (syn == 0) ? aw0 : (syn == 1) ? aw1 : aw2;
    const float* ab = (syn == 0) ? ab0 : (syn == 1) ? ab1 : ab2;
    int row  = blockIdx.x * 8 + (threadIdx.x >> 5);
    int lane = threadIdx.x & 31;
    if (row >= 2 * H * RANKV) return;
    const float* ar = aw + (size_t)row * WDIM;
    float s = 0.f;
    #pragma unroll 4
    for (int t = lane; t < WDIM; t += 32) s += ar[t] * w[t];
    #pragma unroll
    for (int o = 16; o; o >>= 1) s += __shfl_xor_sync(0xffffffffu, s, o);
    if (lane == 0) g_styles[syn][row] = s + ab[row];
}

// ---------------- modulated + row-normalized weight, transposed store ----------------
__global__ void k_modweight(const float* __restrict__ w0,
                            const float* __restrict__ w1,
                            const float* __restrict__ w2)
{
    int syn = blockIdx.y;
    int i   = blockIdx.x;      // c_out
    int j   = threadIdx.x;     // c_in
    const float* weight = (syn == 0) ? w0 : (syn == 1) ? w1 : w2;
    const float* st = g_styles[syn];
    __shared__ float L[RANKV];
    __shared__ float red[H];
    if (j < RANKV) L[j] = st[i * RANKV + j];
    __syncthreads();
    const float inv_sqrt_rank = 0.31622776601683794f;
    float mod = 0.f;
    #pragma unroll
    for (int r = 0; r < RANKV; r++) mod += L[r] * st[H * RANKV + r * H + j];
    float wv = weight[i * H + j] * (mod * inv_sqrt_rank + 1.0f);
    red[j] = wv * wv;
    __syncthreads();
    for (int o = 128; o; o >>= 1) { if (j < o) red[j] += red[j + o]; __syncthreads(); }
    float norm = sqrtf(red[0]) + 1e-8f;
    g_WT[syn][j * H + i] = wv / norm;
}

// ---------------- C1 = I + cat1^T ; E2 = I + cat2^T ----------------
__global__ void k_prep_ce(const float* __restrict__ cat1_w,
                          const float* __restrict__ cat2_w)
{
    int idx = blockIdx.x * blockDim.x + threadIdx.x;
    int i = idx >> 8, k = idx & 255;
    float eye = (i == k) ? 1.f : 0.f;
    g_C1[k * H + i] = cat1_w[i * H + k] + eye;
    g_E2[k * H + i] = cat2_w[i * H + k] + eye;
}

// ---------------- NM2 = nm_w^T @ E2 ; b2 = cat1_b + cat2_b + nm_b @ E2 ----------------
__global__ void k_prep_nm(const float* __restrict__ nm_w,
                          const float* __restrict__ nm_b,
                          const float* __restrict__ cat2_b,
                          const float* __restrict__ cat1_b)
{
    int k = blockIdx.x;        // 0..127
    int i = threadIdx.x;       // 0..255
    float s = 0.f;
    #pragma unroll 8
    for (int m = 0; m < H; m++) s += nm_w[m * INDIM + k] * g_E2[m * H + i];
    g_NM2[k * H + i] = s;
    if (k == 0) {
        float b = cat1_b[i] + cat2_b[i];
        for (int m = 0; m < H; m++) b += nm_b[m] * g_E2[m * H + i];
        g_b2[i] = b;
    }
}

// ---------------- agg init ----------------
__global__ void k_agg_init(const float* __restrict__ edge_bias, int n)
{
    int idx = blockIdx.x * blockDim.x + threadIdx.x;
    if (idx >= n * (H / 4)) return;
    float4 eb = ((const float4*)edge_bias)[idx & 63];
    ((float4*)g_agg)[idx] = eb;
}

// ---------------- scatter-add ----------------
__global__ void k_scatter(const int* __restrict__ ei,
                          const float* __restrict__ nw, int E)
{
    int e = blockIdx.x * 8 + (threadIdx.x >> 5);
    if (e >= E) return;
    int lane = threadIdx.x & 31;
    int s = ei[e];
    int d = ei[E + e];
    const float4* srcp = (const float4*)(nw + (size_t)s * H);
    float4*       dstp = (float4*)(g_agg + (size_t)d * H);
    #pragma unroll
    for (int t = 0; t < 2; t++) {
        int c = lane + t * 32;
        float4 v = srcp[c];
        asm volatile("red.global.add.v4.f32 [%0], {%1,%2,%3,%4};"
                     :: "l"((float*)(dstp + c)),
                        "f"(v.x), "f"(v.y), "f"(v.z), "f"(v.w)
                     : "memory");
    }
}

// ================= tf32 tensor-core GEMM with 3xTF32 split =================
// C[M,256] = leaky( [A0 | A1] @ [B0 ; B1] + bias ),  A0:[M,K0] A1:[M,K1]
#define BM 128
#define BN 128
#define BKT 16
#define ASTRIDE 20      // banks (4r+c) bijective
#define BSTRIDE 136     // banks (8c+n) bijective

__device__ __forceinline__ void split_tf32(float x, uint32_t& hi, uint32_t& lo)
{
    uint32_t h;
    asm("cvt.rna.tf32.f32 %0, %1;" : "=r"(h) : "f"(x));
    float l = x - __uint_as_float(h);
    asm("cvt.rna.tf32.f32 %0, %1;" : "=r"(lo) : "f"(l));
    hi = h;
}

__device__ __forceinline__ void mma8(float* c, const uint32_t* a, const uint32_t* b)
{
    asm volatile("mma.sync.aligned.m16n8k8.row.col.f32.tf32.tf32.f32 "
                 "{%0,%1,%2,%3}, {%4,%5,%6,%7}, {%8,%9}, {%0,%1,%2,%3};"
                 : "+f"(c[0]), "+f"(c[1]), "+f"(c[2]), "+f"(c[3])
                 : "r"(a[0]), "r"(a[1]), "r"(a[2]), "r"(a[3]),
                   "r"(b[0]), "r"(b[1]));
}

__global__ void __launch_bounds__(256) k_gemm_tc(
    const float* __restrict__ A0, int K0,
    const float* __restrict__ A1, int K1,
    const float* __restrict__ B0, const float* __restrict__ B1,
    float* __restrict__ C, int M,
    const float* __restrict__ bias)
{
    __shared__ float As[2][BM * ASTRIDE];
    __shared__ float Bs[2][BKT * BSTRIDE];

    const int tid  = threadIdx.x;
    const int lane = tid & 31;
    const int wid  = tid >> 5;
    const int wm   = wid & 1;          // 2 warp-rows of 64
    const int wn   = wid >> 1;         // 4 warp-cols of 32
    const int gr   = lane >> 2;        // groupID
    const int tg   = lane & 3;         // thread-in-group
    const int mBase = blockIdx.x * BM;
    const int nBase = blockIdx.y * BN;

    // load indices
    const int arow = tid >> 2;             // 0..63, +64 for 2nd
    const int acol = (tid & 3) * 4;
    const int brow = tid >> 5;             // 0..7, +8 for 2nd
    const int bcol = (lane) * 4;

    const int T = (K0 + K1) / BKT;

    float4 av0, av1, bv0, bv1;

    auto fetch = [&](int t) {
        int k0 = t * BKT;
        const float* Ap; int lda_, kc;
        const float* Bp;
        if (k0 < K0) { Ap = A0; lda_ = K0; kc = k0;      Bp = B0 + (size_t)k0 * H; }
        else         { Ap = A1; lda_ = K1; kc = k0 - K0; Bp = B1 + (size_t)(k0 - K0) * H; }
        int r0 = mBase + arow, r1 = r0 + 64;
        av0 = (r0 < M) ? *(const float4*)(Ap + (size_t)r0 * lda_ + kc + acol)
                       : make_float4(0, 0, 0, 0);
        av1 = (r1 < M) ? *(const float4*)(Ap + (size_t)r1 * lda_ + kc + acol)
                       : make_float4(0, 0, 0, 0);
        bv0 = *(const float4*)(Bp + (size_t)brow * H + nBase + bcol);
        bv1 = *(const float4*)(Bp + (size_t)(brow + 8) * H + nBase + bcol);
    };
    auto stage = [&](int buf) {
        *(float4*)&As[buf][arow * ASTRIDE + acol]        = av0;
        *(float4*)&As[buf][(arow + 64) * ASTRIDE + acol] = av1;
        *(float4*)&Bs[buf][brow * BSTRIDE + bcol]        = bv0;
        *(float4*)&Bs[buf][(brow + 8) * BSTRIDE + bcol]  = bv1;
    };

    float acc[4][4][4];
    #pragma unroll
    for (int i = 0; i < 4; i++)
        #pragma unroll
        for (int j = 0; j < 4; j++)
            #pragma unroll
            for (int q = 0; q < 4; q++) acc[i][j][q] = 0.f;

    fetch(0);
    stage(0);
    __syncthreads();

    for (int t = 0; t < T; t++) {
        if (t + 1 < T) fetch(t + 1);
        const float* as = As[t & 1];
        const float* bs = Bs[t & 1];
        #pragma unroll
        for (int kk = 0; kk < BKT; kk += 8) {
            uint32_t aH[4][4], aL[4][4], bH[4][2], bL[4][2];
            #pragma unroll
            for (int mt = 0; mt < 4; mt++) {
                int mr = wm * 64 + mt * 16 + gr;
                split_tf32(as[mr * ASTRIDE + kk + tg],           aH[mt][0], aL[mt][0]);
                split_tf32(as[(mr + 8) * ASTRIDE + kk + tg],     aH[mt][1], aL[mt][1]);
                split_tf32(as[mr * ASTRIDE + kk + tg + 4],       aH[mt][2], aL[mt][2]);
                split_tf32(as[(mr + 8) * ASTRIDE + kk + tg + 4], aH[mt][3], aL[mt][3]);
            }
            #pragma unroll
            for (int nt = 0; nt < 4; nt++) {
                int nc = wn * 32 + nt * 8 + gr;
                split_tf32(bs[(kk + tg) * BSTRIDE + nc],     bH[nt][0], bL[nt][0]);
                split_tf32(bs[(kk + tg + 4) * BSTRIDE + nc], bH[nt][1], bL[nt][1]);
            }
            #pragma unroll
            for (int mt = 0; mt < 4; mt++)
                #pragma unroll
                for (int nt = 0; nt < 4; nt++) {
                    mma8(acc[mt][nt], aH[mt], bH[nt]);
                    mma8(acc[mt][nt], aH[mt], bL[nt]);
                    mma8(acc[mt][nt], aL[mt], bH[nt]);
                }
        }
        if (t + 1 < T) {
            stage((t + 1) & 1);
            __syncthreads();
        }
    }

    // epilogue: bias + leaky, float2 stores
    #pragma unroll
    for (int nt = 0; nt < 4; nt++) {
        int col = nBase + wn * 32 + nt * 8 + tg * 2;
        float b0 = bias[col], b1 = bias[col + 1];
        #pragma unroll
        for (int mt = 0; mt < 4; mt++) {
            int r0 = mBase + wm * 64 + mt * 16 + gr;
            float v0 = acc[mt][nt][0] + b0;
            float v1 = acc[mt][nt][1] + b1;
            float v2 = acc[mt][nt][2] + b0;
            float v3 = acc[mt][nt][3] + b1;
            v0 = (v0 >= 0.f) ? v0 : SLOPE * v0;
            v1 = (v1 >= 0.f) ? v1 : SLOPE * v1;
            v2 = (v2 >= 0.f) ? v2 : SLOPE * v2;
            v3 = (v3 >= 0.f) ? v3 : SLOPE * v3;
            if (r0 < M)     *(float2*)(C + (size_t)r0 * H + col)       = make_float2(v0, v1);
            if (r0 + 8 < M) *(float2*)(C + (size_t)(r0 + 8) * H + col) = make_float2(v2, v3);
        }
    }
}

// ---------------- launch ----------------
extern "C" void kernel_launch(void* const* d_in, const int* in_sizes, int n_in,
                              void* d_out, int out_size)
{
    const float* x          = (const float*)d_in[0];
    const int*   edge_index = (const int*)  d_in[1];
    const float* w          = (const float*)d_in[2];
    const float* node_w     = (const float*)d_in[3];
    const float* edge_bias  = (const float*)d_in[4];
    const float* le_aw      = (const float*)d_in[5];
    const float* le_ab      = (const float*)d_in[6];
    const float* le_weight  = (const float*)d_in[7];
    const float* le_bias    = (const float*)d_in[8];
    const float* cat1_w     = (const float*)d_in[10];
    const float* cat1_b     = (const float*)d_in[11];
    const float* cat2_w     = (const float*)d_in[12];
    const float* cat2_b     = (const float*)d_in[13];
    const float* nm_w       = (const float*)d_in[14];
    const float* nm_b       = (const float*)d_in[15];
    const float* f1_aw      = (const float*)d_in[16];
    const float* f1_ab      = (const float*)d_in[17];
    const float* f1_weight  = (const float*)d_in[18];
    const float* f1_bias    = (const float*)d_in[19];
    const float* f2_aw      = (const float*)d_in[21];
    const float* f2_ab      = (const float*)d_in[22];
    const float* f2_weight  = (const float*)d_in[23];
    const float* f2_bias    = (const float*)d_in[24];

    int N = in_sizes[3] / H;
    int E = in_sizes[1] / 2;

    float *agg, *b1, *b2, *wt, *c1, *nm2, *b2v;
    cudaGetSymbolAddress((void**)&agg, g_agg);
    cudaGetSymbolAddress((void**)&b1,  g_buf1);
    cudaGetSymbolAddress((void**)&b2,  g_buf2);
    cudaGetSymbolAddress((void**)&wt,  g_WT);
    cudaGetSymbolAddress((void**)&c1,  g_C1);
    cudaGetSymbolAddress((void**)&nm2, g_NM2);
    cudaGetSymbolAddress((void**)&b2v, g_b2);

    // weight prep (tiny)
    k_styles   <<<dim3(2 * H * RANKV / 8, 3), 256>>>(le_aw, le_ab, f1_aw, f1_ab, f2_aw, f2_ab, w);
    k_modweight<<<dim3(H, 3), 256>>>(le_weight, f1_weight, f2_weight);
    k_prep_ce  <<<H * H / 256, 256>>>(cat1_w, cat2_w);
    k_prep_nm  <<<INDIM, 256>>>(nm_w, nm_b, cat2_b, cat1_b);

    // graph aggregation
    k_agg_init <<<(N * (H / 4) + 255) / 256, 256>>>(edge_bias, N);
    k_scatter  <<<(E + 7) / 8, 256>>>(edge_index, node_w, E);

    dim3 gg((N + BM - 1) / BM, H / BN);
    // G1: b1 = leaky(agg @ WT_le + le_bias)
    k_gemm_tc<<<gg, 256>>>(agg, H, nullptr, 0, wt + 0 * H * H, nullptr, b1, N, le_bias);
    // G2 (fused): b2 = leaky(b1 @ C1 + x @ NM2 + b2v)
    k_gemm_tc<<<gg, 256>>>(b1, H, x, INDIM, c1, nm2, b2, N, b2v);
    // G3: b1 = leaky(b2 @ WT_f1 + f1_bias)
    k_gemm_tc<<<gg, 256>>>(b2, H, nullptr, 0, wt + 1 * H * H, nullptr, b1, N, f1_bias);
    // G4: out = leaky(b1 @ WT_f2 + f2_bias)
    k_gemm_tc<<<gg, 256>>>(b1, H, nullptr, 0, wt + 2 * H * H, nullptr, (float*)d_out, N, f2_bias);
}

// round 4
// speedup vs baseline: 1.7349x; 1.4333x over previous
#include <cuda_runtime.h>
#include <cuda_bf16.h>
#include <stdint.h>
#include <math.h>

#define H 256
#define INDIM 128
#define WDIM 512
#define RANKV 10
#define NMAX 50000
#define SLOPE 0.01f

// ---------------- device scratch ----------------
__device__ float g_agg [NMAX * H];
__device__ float g_styles[3][2 * H * RANKV];
__device__ __nv_bfloat16 g_ah[NMAX * H],  g_al[NMAX * H];     // activation ping (hi/lo)
__device__ __nv_bfloat16 g_bh[NMAX * H],  g_bl[NMAX * H];     // activation pong
__device__ __nv_bfloat16 g_xh[NMAX * INDIM], g_xl[NMAX * INDIM];
__device__ __nv_bfloat16 g_Wh[3][H * H],  g_Wl[3][H * H];     // modded weights [n][k]
__device__ __nv_bfloat16 g_C1h[H * H],    g_C1l[H * H];       // I + cat1^T as [n][k]
__device__ __nv_bfloat16 g_NMh[H * INDIM], g_NMl[H * INDIM];  // fused node-mlp [n][k]
__device__ float g_b2[H];

// ---------------- helpers ----------------
__device__ __forceinline__ void split_bf(float x, __nv_bfloat16& h, __nv_bfloat16& l)
{
    h = __float2bfloat16(x);
    l = __float2bfloat16(x - __bfloat162float(h));
}

__device__ __forceinline__ uint32_t s2u(const void* p)
{
    uint32_t a;
    asm("{ .reg .u64 t; cvta.to.shared.u64 t, %1; cvt.u32.u64 %0, t; }" : "=r"(a) : "l"(p));
    return a;
}

#define LDSM4(r0, r1, r2, r3, addr) \
    asm volatile("ldmatrix.sync.aligned.m8n8.x4.shared.b16 {%0,%1,%2,%3}, [%4];" \
                 : "=r"(r0), "=r"(r1), "=r"(r2), "=r"(r3) : "r"(addr))

#define MMA16816(c, a, b) \
    asm volatile("mma.sync.aligned.m16n8k16.row.col.f32.bf16.bf16.f32 " \
                 "{%0,%1,%2,%3},{%4,%5,%6,%7},{%8,%9},{%0,%1,%2,%3};" \
                 : "+f"((c)[0]), "+f"((c)[1]), "+f"((c)[2]), "+f"((c)[3]) \
                 : "r"((a)[0]), "r"((a)[1]), "r"((a)[2]), "r"((a)[3]), \
                   "r"((b)[0]), "r"((b)[1]))

#define CPA16(dst, src) \
    asm volatile("cp.async.cg.shared.global [%0], [%1], 16;" :: "r"(dst), "l"(src) : "memory")
#define CPA_COMMIT() asm volatile("cp.async.commit_group;" ::: "memory")
#define CPA_WAIT1()  asm volatile("cp.async.wait_group 1;" ::: "memory")
#define CPA_WAIT0()  asm volatile("cp.async.wait_group 0;" ::: "memory")

// ---------------- styles = aw @ w + ab ----------------
__global__ void k_styles(const float* __restrict__ aw0, const float* __restrict__ ab0,
                         const float* __restrict__ aw1, const float* __restrict__ ab1,
                         const float* __restrict__ aw2, const float* __restrict__ ab2,
                         const float* __restrict__ w)
{
    int syn = blockIdx.y;
    const float* aw = (syn == 0) ? aw0 : (syn == 1) ? aw1 : aw2;
    const float* ab = (syn == 0) ? ab0 : (syn == 1) ? ab1 : ab2;
    int row  = blockIdx.x * 8 + (threadIdx.x >> 5);
    int lane = threadIdx.x & 31;
    if (row >= 2 * H * RANKV) return;
    const float* ar = aw + (size_t)row * WDIM;
    float s = 0.f;
    #pragma unroll 4
    for (int t = lane; t < WDIM; t += 32) s += ar[t] * w[t];
    #pragma unroll
    for (int o = 16; o; o >>= 1) s += __shfl_xor_sync(0xffffffffu, s, o);
    if (lane == 0) g_styles[syn][row] = s + ab[row];
}

// ---------------- modulated + row-normalized weight → bf16 split [n][k] ----------------
__global__ void k_modweight(const float* __restrict__ w0,
                            const float* __restrict__ w1,
                            const float* __restrict__ w2)
{
    int syn = blockIdx.y;
    int i   = blockIdx.x;      // c_out = n
    int j   = threadIdx.x;     // c_in = k
    const float* weight = (syn == 0) ? w0 : (syn == 1) ? w1 : w2;
    const float* st = g_styles[syn];
    __shared__ float L[RANKV];
    __shared__ float red[H];
    if (j < RANKV) L[j] = st[i * RANKV + j];
    __syncthreads();
    const float inv_sqrt_rank = 0.31622776601683794f;
    float mod = 0.f;
    #pragma unroll
    for (int r = 0; r < RANKV; r++) mod += L[r] * st[H * RANKV + r * H + j];
    float wv = weight[i * H + j] * (mod * inv_sqrt_rank + 1.0f);
    red[j] = wv * wv;
    __syncthreads();
    for (int o = 128; o; o >>= 1) { if (j < o) red[j] += red[j + o]; __syncthreads(); }
    float norm = sqrtf(red[0]) + 1e-8f;
    __nv_bfloat16 h, l;
    split_bf(wv / norm, h, l);
    g_Wh[syn][i * H + j] = h;
    g_Wl[syn][i * H + j] = l;
}

// ---------------- C1 = cat1_w + I, split [n][k] ----------------
__global__ void k_prep_c1(const float* __restrict__ cat1_w)
{
    int idx = blockIdx.x * blockDim.x + threadIdx.x;
    int n = idx >> 8, k = idx & 255;
    __nv_bfloat16 h, l;
    split_bf(cat1_w[idx] + ((n == k) ? 1.f : 0.f), h, l);
    g_C1h[idx] = h;
    g_C1l[idx] = l;
}

// ---------------- NM[n][k] = nm_w[n][k] + sum_m cat2_w[n][m]*nm_w[m][k] ----------------
__global__ void k_prep_nm(const float* __restrict__ nm_w,
                          const float* __restrict__ cat2_w)
{
    int n = blockIdx.x;        // 0..255
    int k = threadIdx.x;       // 0..127
    __shared__ float c2[H];
    c2[k] = cat2_w[n * H + k];
    c2[k + 128] = cat2_w[n * H + k + 128];
    __syncthreads();
    float s = nm_w[n * INDIM + k];
    #pragma unroll 8
    for (int m = 0; m < H; m++) s += c2[m] * nm_w[m * INDIM + k];
    __nv_bfloat16 h, l;
    split_bf(s, h, l);
    g_NMh[n * INDIM + k] = h;
    g_NMl[n * INDIM + k] = l;
}

// ---------------- b2[n] ----------------
__global__ void k_prep_b2(const float* __restrict__ cat1_b,
                          const float* __restrict__ cat2_b,
                          const float* __restrict__ nm_b,
                          const float* __restrict__ cat2_w)
{
    int n = threadIdx.x;
    float b = cat1_b[n] + cat2_b[n] + nm_b[n];
    for (int m = 0; m < H; m++) b += cat2_w[n * H + m] * nm_b[m];
    g_b2[n] = b;
}

// ---------------- agg init ----------------
__global__ void k_agg_init(const float* __restrict__ edge_bias, int n)
{
    int idx = blockIdx.x * blockDim.x + threadIdx.x;
    if (idx >= n * (H / 4)) return;
    float4 eb = ((const float4*)edge_bias)[idx & 63];
    ((float4*)g_agg)[idx] = eb;
}

// ---------------- scatter-add ----------------
__global__ void k_scatter(const int* __restrict__ ei,
                          const float* __restrict__ nw, int E)
{
    int e = blockIdx.x * 8 + (threadIdx.x >> 5);
    if (e >= E) return;
    int lane = threadIdx.x & 31;
    int s = ei[e];
    int d = ei[E + e];
    const float4* srcp = (const float4*)(nw + (size_t)s * H);
    float4*       dstp = (float4*)(g_agg + (size_t)d * H);
    #pragma unroll
    for (int t = 0; t < 2; t++) {
        int c = lane + t * 32;
        float4 v = srcp[c];
        asm volatile("red.global.add.v4.f32 [%0], {%1,%2,%3,%4};"
                     :: "l"((float*)(dstp + c)),
                        "f"(v.x), "f"(v.y), "f"(v.z), "f"(v.w)
                     : "memory");
    }
}

// ---------------- fp32 → bf16 hi/lo split (activations) ----------------
__global__ void k_split(const float* __restrict__ src,
                        __nv_bfloat16* __restrict__ hi,
                        __nv_bfloat16* __restrict__ lo, int n4)
{
    int idx = blockIdx.x * blockDim.x + threadIdx.x;
    if (idx >= n4) return;
    float4 v = ((const float4*)src)[idx];
    __nv_bfloat162 h0 = __floats2bfloat162_rn(v.x, v.y);
    __nv_bfloat162 h1 = __floats2bfloat162_rn(v.z, v.w);
    __nv_bfloat162 l0 = __floats2bfloat162_rn(v.x - __low2float(h0), v.y - __high2float(h0));
    __nv_bfloat162 l1 = __floats2bfloat162_rn(v.z - __low2float(h1), v.w - __high2float(h1));
    ((__nv_bfloat162*)hi)[idx * 2]     = h0;
    ((__nv_bfloat162*)hi)[idx * 2 + 1] = h1;
    ((__nv_bfloat162*)lo)[idx * 2]     = l0;
    ((__nv_bfloat162*)lo)[idx * 2 + 1] = l1;
}

// ================= bf16 split-3 tensor GEMM =================
// C[M,256] = leaky( [A0|A1] @ [B0;B1]^T + bias )
// A given as bf16 hi/lo [M][K]; B as bf16 hi/lo [n][k].
// Output: fp32 (outF) or bf16 hi/lo split (outH/outL).
#define TK 32
#define PITCH 80                       // 64B data + 16B pad: conflict-free ldmatrix
#define TILE_B (128 * PITCH)           // 10240
#define STAGE_B (4 * TILE_B)           // Ah, Al, Bh, Bl
#define GEMM_SMEM (2 * STAGE_B)        // 81920

__global__ void __launch_bounds__(256)
k_gemm_bf(const __nv_bfloat16* __restrict__ Ah0, const __nv_bfloat16* __restrict__ Al0, int K0,
          const __nv_bfloat16* __restrict__ Ah1, const __nv_bfloat16* __restrict__ Al1, int K1,
          const __nv_bfloat16* __restrict__ Bh0, const __nv_bfloat16* __restrict__ Bl0,
          const __nv_bfloat16* __restrict__ Bh1, const __nv_bfloat16* __restrict__ Bl1,
          float* __restrict__ outF,
          __nv_bfloat16* __restrict__ outH, __nv_bfloat16* __restrict__ outL,
          int M, const float* __restrict__ bias)
{
    extern __shared__ char smem_[];
    const uint32_t sbase = s2u(smem_);
    const int tid  = threadIdx.x;
    const int lane = tid & 31;
    const int wid  = tid >> 5;
    const int wm   = wid & 1;          // m-half (64 rows)
    const int wn   = wid >> 1;         // n-group (32 cols)
    const int gr   = lane >> 2;
    const int tg   = lane & 3;
    const int mBase = blockIdx.x * 128;
    const int nBase = blockIdx.y * 128;

    // staging indices: 512 16B-units per tile, thread does 2 per tile
    const int srow = tid >> 1;               // 0..127
    const int sq0  = (tid & 1) * 2;          // 0 or 2 (16B unit)

    const int T = (K0 + K1) / TK;

    auto issue = [&](int t) {
        const int kc0 = t * TK;
        const __nv_bfloat16 *Ah, *Al, *Bh, *Bl;
        int lda, ldb, kc;
        if (kc0 < K0) { Ah = Ah0; Al = Al0; Bh = Bh0; Bl = Bl0; lda = K0; ldb = K0; kc = kc0; }
        else          { Ah = Ah1; Al = Al1; Bh = Bh1; Bl = Bl1; lda = K1; ldb = K1; kc = kc0 - K0; }
        uint32_t st = sbase + (t & 1) * STAGE_B;
        int arow = mBase + srow; if (arow >= M) arow = M - 1;
        const size_t aoff = (size_t)arow * lda + kc + sq0 * 8;
        const size_t boff = (size_t)(nBase + srow) * ldb + kc + sq0 * 8;
        uint32_t d = st + srow * PITCH + sq0 * 16;
        CPA16(d,                         Ah + aoff);
        CPA16(d + 16,                    Ah + aoff + 8);
        CPA16(d + TILE_B,                Al + aoff);
        CPA16(d + TILE_B + 16,           Al + aoff + 8);
        CPA16(d + 2 * TILE_B,            Bh + boff);
        CPA16(d + 2 * TILE_B + 16,       Bh + boff + 8);
        CPA16(d + 3 * TILE_B,            Bl + boff);
        CPA16(d + 3 * TILE_B + 16,       Bl + boff + 8);
        CPA_COMMIT();
    };

    float acc[4][4][4];
    #pragma unroll
    for (int i = 0; i < 4; i++)
        #pragma unroll
        for (int j = 0; j < 4; j++)
            #pragma unroll
            for (int q = 0; q < 4; q++) acc[i][j][q] = 0.f;

    // ldmatrix lane address components
    const int a_row = (lane & 7) + ((lane >> 3) & 1) * 8;
    const int a_kb  = (lane >> 4) * 16;
    const int b_row = (lane & 7) + ((lane >> 4) & 1) * 8;
    const int b_kb  = ((lane >> 3) & 1) * 16;

    issue(0);

    for (int t = 0; t < T; t++) {
        if (t + 1 < T) { issue(t + 1); CPA_WAIT1(); }
        else           { CPA_WAIT0(); }
        __syncthreads();

        uint32_t st = sbase + (t & 1) * STAGE_B;
        uint32_t sAh = st, sAl = st + TILE_B, sBh = st + 2 * TILE_B, sBl = st + 3 * TILE_B;

        #pragma unroll
        for (int s = 0; s < 2; s++) {
            const int skb = s * 32;
            uint32_t bH[4][2], bL[4][2];
            #pragma unroll
            for (int p = 0; p < 2; p++) {
                uint32_t ba = (wn * 32 + p * 16 + b_row) * PITCH + skb + b_kb;
                LDSM4(bH[2 * p][0], bH[2 * p][1], bH[2 * p + 1][0], bH[2 * p + 1][1], sBh + ba);
                LDSM4(bL[2 * p][0], bL[2 * p][1], bL[2 * p + 1][0], bL[2 * p + 1][1], sBl + ba);
            }
            #pragma unroll
            for (int mt = 0; mt < 4; mt++) {
                uint32_t aH[4], aL[4];
                uint32_t aa = (wm * 64 + mt * 16 + a_row) * PITCH + skb + a_kb;
                LDSM4(aH[0], aH[1], aH[2], aH[3], sAh + aa);
                LDSM4(aL[0], aL[1], aL[2], aL[3], sAl + aa);
                #pragma unroll
                for (int nt = 0; nt < 4; nt++) {
                    MMA16816(acc[mt][nt], aH, bH[nt]);
                    MMA16816(acc[mt][nt], aH, bL[nt]);
                    MMA16816(acc[mt][nt], aL, bH[nt]);
                }
            }
        }
        __syncthreads();
    }

    // ---- epilogue: bias + leaky; fp32 or bf16-split stores ----
    #pragma unroll
    for (int nt = 0; nt < 4; nt++) {
        int col = nBase + wn * 32 + nt * 8 + tg * 2;
        float b0 = bias[col], b1 = bias[col + 1];
        #pragma unroll
        for (int mt = 0; mt < 4; mt++) {
            int r0 = mBase + wm * 64 + mt * 16 + gr;
            int r1 = r0 + 8;
            float v0 = acc[mt][nt][0] + b0;
            float v1 = acc[mt][nt][1] + b1;
            float v2 = acc[mt][nt][2] + b0;
            float v3 = acc[mt][nt][3] + b1;
            v0 = (v0 >= 0.f) ? v0 : SLOPE * v0;
            v1 = (v1 >= 0.f) ? v1 : SLOPE * v1;
            v2 = (v2 >= 0.f) ? v2 : SLOPE * v2;
            v3 = (v3 >= 0.f) ? v3 : SLOPE * v3;
            if (outF) {
                if (r0 < M) *(float2*)(outF + (size_t)r0 * H + col) = make_float2(v0, v1);
                if (r1 < M) *(float2*)(outF + (size_t)r1 * H + col) = make_float2(v2, v3);
            } else {
                __nv_bfloat162 h0 = __floats2bfloat162_rn(v0, v1);
                __nv_bfloat162 h1 = __floats2bfloat162_rn(v2, v3);
                __nv_bfloat162 l0 = __floats2bfloat162_rn(v0 - __low2float(h0), v1 - __high2float(h0));
                __nv_bfloat162 l1 = __floats2bfloat162_rn(v2 - __low2float(h1), v3 - __high2float(h1));
                if (r0 < M) {
                    *(__nv_bfloat162*)(outH + (size_t)r0 * H + col) = h0;
                    *(__nv_bfloat162*)(outL + (size_t)r0 * H + col) = l0;
                }
                if (r1 < M) {
                    *(__nv_bfloat162*)(outH + (size_t)r1 * H + col) = h1;
                    *(__nv_bfloat162*)(outL + (size_t)r1 * H + col) = l1;
                }
            }
        }
    }
}

// ---------------- launch ----------------
extern "C" void kernel_launch(void* const* d_in, const int* in_sizes, int n_in,
                              void* d_out, int out_size)
{
    const float* x          = (const float*)d_in[0];
    const int*   edge_index = (const int*)  d_in[1];
    const float* w          = (const float*)d_in[2];
    const float* node_w     = (const float*)d_in[3];
    const float* edge_bias  = (const float*)d_in[4];
    const float* le_aw      = (const float*)d_in[5];
    const float* le_ab      = (const float*)d_in[6];
    const float* le_weight  = (const float*)d_in[7];
    const float* le_bias    = (const float*)d_in[8];
    const float* cat1_w     = (const float*)d_in[10];
    const float* cat1_b     = (const float*)d_in[11];
    const float* cat2_w     = (const float*)d_in[12];
    const float* cat2_b     = (const float*)d_in[13];
    const float* nm_w       = (const float*)d_in[14];
    const float* nm_b       = (const float*)d_in[15];
    const float* f1_aw      = (const float*)d_in[16];
    const float* f1_ab      = (const float*)d_in[17];
    const float* f1_weight  = (const float*)d_in[18];
    const float* f1_bias    = (const float*)d_in[19];
    const float* f2_aw      = (const float*)d_in[21];
    const float* f2_ab      = (const float*)d_in[22];
    const float* f2_weight  = (const float*)d_in[23];
    const float* f2_bias    = (const float*)d_in[24];

    int N = in_sizes[3] / H;
    int E = in_sizes[1] / 2;

    float *agg, *b2v;
    __nv_bfloat16 *ah, *al, *bh, *bl, *xh, *xl, *wh, *wl, *c1h, *c1l, *nmh, *nml;
    cudaGetSymbolAddress((void**)&agg, g_agg);
    cudaGetSymbolAddress((void**)&b2v, g_b2);
    cudaGetSymbolAddress((void**)&ah,  g_ah);
    cudaGetSymbolAddress((void**)&al,  g_al);
    cudaGetSymbolAddress((void**)&bh,  g_bh);
    cudaGetSymbolAddress((void**)&bl,  g_bl);
    cudaGetSymbolAddress((void**)&xh,  g_xh);
    cudaGetSymbolAddress((void**)&xl,  g_xl);
    cudaGetSymbolAddress((void**)&wh,  g_Wh);
    cudaGetSymbolAddress((void**)&wl,  g_Wl);
    cudaGetSymbolAddress((void**)&c1h, g_C1h);
    cudaGetSymbolAddress((void**)&c1l, g_C1l);
    cudaGetSymbolAddress((void**)&nmh, g_NMh);
    cudaGetSymbolAddress((void**)&nml, g_NMl);

    static int attr_done = 0;
    if (!attr_done) {
        cudaFuncSetAttribute(k_gemm_bf, cudaFuncAttributeMaxDynamicSharedMemorySize, GEMM_SMEM);
        attr_done = 1;
    }

    // weight prep
    k_styles   <<<dim3(2 * H * RANKV / 8, 3), 256>>>(le_aw, le_ab, f1_aw, f1_ab, f2_aw, f2_ab, w);
    k_modweight<<<dim3(H, 3), 256>>>(le_weight, f1_weight, f2_weight);
    k_prep_c1  <<<H * H / 256, 256>>>(cat1_w);
    k_prep_nm  <<<H, INDIM>>>(nm_w, cat2_w);
    k_prep_b2  <<<1, H>>>(cat1_b, cat2_b, nm_b, cat2_w);

    // graph aggregation + splits
    k_agg_init <<<(N * (H / 4) + 255) / 256, 256>>>(edge_bias, N);
    k_scatter  <<<(E + 7) / 8, 256>>>(edge_index, node_w, E);
    k_split    <<<(N * H / 4 + 255) / 256, 256>>>(agg, ah, al, N * H / 4);
    k_split    <<<(N * INDIM / 4 + 255) / 256, 256>>>(x, xh, xl, N * INDIM / 4);

    dim3 gg((N + 127) / 128, 2);
    // G1: b = leaky(agg @ W_le^T + le_bias)        [split out]
    k_gemm_bf<<<gg, 256, GEMM_SMEM>>>(ah, al, H, nullptr, nullptr, 0,
                                      wh + 0 * H * H, wl + 0 * H * H, nullptr, nullptr,
                                      nullptr, bh, bl, N, le_bias);
    // G2: a = leaky(b @ (I+cat1^T) + x @ NM + b2)  [fused K=384, split out]
    k_gemm_bf<<<gg, 256, GEMM_SMEM>>>(bh, bl, H, xh, xl, INDIM,
                                      c1h, c1l, nmh, nml,
                                      nullptr, ah, al, N, b2v);
    // G3: b = leaky(a @ W_f1^T + f1_bias)          [split out]
    k_gemm_bf<<<gg, 256, GEMM_SMEM>>>(ah, al, H, nullptr, nullptr, 0,
                                      wh + 1 * H * H, wl + 1 * H * H, nullptr, nullptr,
                                      nullptr, bh, bl, N, f1_bias);
    // G4: out = leaky(b @ W_f2^T + f2_bias)        [fp32 out]
    k_gemm_bf<<<gg, 256, GEMM_SMEM>>>(bh, bl, H, nullptr, nullptr, 0,
                                      wh + 2 * H * H, wl + 2 * H * H, nullptr, nullptr,
                                      (float*)d_out, nullptr, nullptr, N, f2_bias);
}

// round 5
// speedup vs baseline: 1.7934x; 1.0337x over previous
#include <cuda_runtime.h>
#include <cuda_bf16.h>
#include <stdint.h>
#include <math.h>

#define H 256
#define INDIM 128
#define WDIM 512
#define RANKV 10
#define NMAX 50000
#define EMAX 800000
#define SLOPE 0.01f

// ---------------- device scratch ----------------
__device__ float g_styles[3][2 * H * RANKV];
__device__ __nv_bfloat16 g_ah[NMAX * H],  g_al[NMAX * H];     // activation ping (hi/lo)
__device__ __nv_bfloat16 g_bh[NMAX * H],  g_bl[NMAX * H];     // activation pong
__device__ __nv_bfloat16 g_xh[NMAX * INDIM], g_xl[NMAX * INDIM];
__device__ __nv_bfloat16 g_Wh[3][H * H],  g_Wl[3][H * H];     // modded weights [n][k]
__device__ __nv_bfloat16 g_C1h[H * H],    g_C1l[H * H];       // I + cat1^T as [n][k]
__device__ __nv_bfloat16 g_NMh[H * INDIM], g_NMl[H * INDIM];  // fused node-mlp [n][k]
__device__ float g_b2[H];
// CSR scratch
__device__ int g_deg[NMAX];
__device__ int g_off[NMAX + 1];
__device__ int g_cur[NMAX];
__device__ int g_eidx[EMAX];

// ---------------- helpers ----------------
__device__ __forceinline__ void split_bf(float x, __nv_bfloat16& h, __nv_bfloat16& l)
{
    h = __float2bfloat16(x);
    l = __float2bfloat16(x - __bfloat162float(h));
}

__device__ __forceinline__ uint32_t s2u(const void* p)
{
    uint32_t a;
    asm("{ .reg .u64 t; cvta.to.shared.u64 t, %1; cvt.u32.u64 %0, t; }" : "=r"(a) : "l"(p));
    return a;
}

#define LDSM4(r0, r1, r2, r3, addr) \
    asm volatile("ldmatrix.sync.aligned.m8n8.x4.shared.b16 {%0,%1,%2,%3}, [%4];" \
                 : "=r"(r0), "=r"(r1), "=r"(r2), "=r"(r3) : "r"(addr))

#define MMA16816(c, a, b) \
    asm volatile("mma.sync.aligned.m16n8k16.row.col.f32.bf16.bf16.f32 " \
                 "{%0,%1,%2,%3},{%4,%5,%6,%7},{%8,%9},{%0,%1,%2,%3};" \
                 : "+f"((c)[0]), "+f"((c)[1]), "+f"((c)[2]), "+f"((c)[3]) \
                 : "r"((a)[0]), "r"((a)[1]), "r"((a)[2]), "r"((a)[3]), \
                   "r"((b)[0]), "r"((b)[1]))

#define CPA16(dst, src) \
    asm volatile("cp.async.cg.shared.global [%0], [%1], 16;" :: "r"(dst), "l"(src) : "memory")
#define CPA_COMMIT() asm volatile("cp.async.commit_group;" ::: "memory")
#define CPA_WAIT1()  asm volatile("cp.async.wait_group 1;" ::: "memory")
#define CPA_WAIT0()  asm volatile("cp.async.wait_group 0;" ::: "memory")

// ---------------- styles = aw @ w + ab ----------------
__global__ void k_styles(const float* __restrict__ aw0, const float* __restrict__ ab0,
                         const float* __restrict__ aw1, const float* __restrict__ ab1,
                         const float* __restrict__ aw2, const float* __restrict__ ab2,
                         const float* __restrict__ w)
{
    int syn = blockIdx.y;
    const float* aw = (syn == 0) ? aw0 : (syn == 1) ? aw1 : aw2;
    const float* ab = (syn == 0) ? ab0 : (syn == 1) ? ab1 : ab2;
    int row  = blockIdx.x * 8 + (threadIdx.x >> 5);
    int lane = threadIdx.x & 31;
    if (row >= 2 * H * RANKV) return;
    const float* ar = aw + (size_t)row * WDIM;
    float s = 0.f;
    #pragma unroll 4
    for (int t = lane; t < WDIM; t += 32) s += ar[t] * w[t];
    #pragma unroll
    for (int o = 16; o; o >>= 1) s += __shfl_xor_sync(0xffffffffu, s, o);
    if (lane == 0) g_styles[syn][row] = s + ab[row];
}

// ---------------- modulated + row-normalized weight → bf16 split [n][k] ----------------
__global__ void k_modweight(const float* __restrict__ w0,
                            const float* __restrict__ w1,
                            const float* __restrict__ w2)
{
    int syn = blockIdx.y;
    int i   = blockIdx.x;      // c_out = n
    int j   = threadIdx.x;     // c_in = k
    const float* weight = (syn == 0) ? w0 : (syn == 1) ? w1 : w2;
    const float* st = g_styles[syn];
    __shared__ float L[RANKV];
    __shared__ float red[H];
    if (j < RANKV) L[j] = st[i * RANKV + j];
    __syncthreads();
    const float inv_sqrt_rank = 0.31622776601683794f;
    float mod = 0.f;
    #pragma unroll
    for (int r = 0; r < RANKV; r++) mod += L[r] * st[H * RANKV + r * H + j];
    float wv = weight[i * H + j] * (mod * inv_sqrt_rank + 1.0f);
    red[j] = wv * wv;
    __syncthreads();
    for (int o = 128; o; o >>= 1) { if (j < o) red[j] += red[j + o]; __syncthreads(); }
    float norm = sqrtf(red[0]) + 1e-8f;
    __nv_bfloat16 h, l;
    split_bf(wv / norm, h, l);
    g_Wh[syn][i * H + j] = h;
    g_Wl[syn][i * H + j] = l;
}

// ---------------- C1 = cat1_w + I, split [n][k] ----------------
__global__ void k_prep_c1(const float* __restrict__ cat1_w)
{
    int idx = blockIdx.x * blockDim.x + threadIdx.x;
    int n = idx >> 8, k = idx & 255;
    __nv_bfloat16 h, l;
    split_bf(cat1_w[idx] + ((n == k) ? 1.f : 0.f), h, l);
    g_C1h[idx] = h;
    g_C1l[idx] = l;
}

// ---------------- NM[n][k] = nm_w[n][k] + sum_m cat2_w[n][m]*nm_w[m][k] ----------------
__global__ void k_prep_nm(const float* __restrict__ nm_w,
                          const float* __restrict__ cat2_w)
{
    int n = blockIdx.x;        // 0..255
    int k = threadIdx.x;       // 0..127
    __shared__ float c2[H];
    c2[k] = cat2_w[n * H + k];
    c2[k + 128] = cat2_w[n * H + k + 128];
    __syncthreads();
    float s = nm_w[n * INDIM + k];
    #pragma unroll 8
    for (int m = 0; m < H; m++) s += c2[m] * nm_w[m * INDIM + k];
    __nv_bfloat16 h, l;
    split_bf(s, h, l);
    g_NMh[n * INDIM + k] = h;
    g_NMl[n * INDIM + k] = l;
}

// ---------------- b2[n] ----------------
__global__ void k_prep_b2(const float* __restrict__ cat1_b,
                          const float* __restrict__ cat2_b,
                          const float* __restrict__ nm_b,
                          const float* __restrict__ cat2_w)
{
    int n = threadIdx.x;
    float b = cat1_b[n] + cat2_b[n] + nm_b[n];
    for (int m = 0; m < H; m++) b += cat2_w[n * H + m] * nm_b[m];
    g_b2[n] = b;
}

// ================= CSR build + gather aggregation =================
__global__ void k_zero_deg(int n)
{
    int i = blockIdx.x * blockDim.x + threadIdx.x;
    if (i < n) g_deg[i] = 0;
}

__global__ void k_hist(const int* __restrict__ ei, int E)
{
    int e = blockIdx.x * blockDim.x + threadIdx.x;
    if (e < E) atomicAdd(&g_deg[ei[E + e]], 1);
}

// single-block exclusive scan over g_deg -> g_off, g_cur
__global__ void k_scan(int n)
{
    __shared__ int sm[1024];
    __shared__ int carry;
    int tid = threadIdx.x;
    if (tid == 0) carry = 0;
    __syncthreads();
    for (int base = 0; base < n; base += 1024) {
        int v = (base + tid < n) ? g_deg[base + tid] : 0;
        sm[tid] = v;
        __syncthreads();
        #pragma unroll
        for (int o = 1; o < 1024; o <<= 1) {
            int t = (tid >= o) ? sm[tid - o] : 0;
            __syncthreads();
            sm[tid] += t;
            __syncthreads();
        }
        int c = carry;
        int excl = c + sm[tid] - v;
        if (base + tid < n) { g_off[base + tid] = excl; g_cur[base + tid] = excl; }
        __syncthreads();
        if (tid == 0) carry = c + sm[1023];
        __syncthreads();
    }
    if (tid == 0) g_off[n] = carry;
}

__global__ void k_fill(const int* __restrict__ ei, int E)
{
    int e = blockIdx.x * blockDim.x + threadIdx.x;
    if (e >= E) return;
    int s = ei[e];
    int d = ei[E + e];
    int p = atomicAdd(&g_cur[d], 1);
    g_eidx[p] = s;
}

// gather: 64 threads per node; acc in registers; fused bias + bf16 split out
__global__ void k_gather(const float* __restrict__ nw,
                         const float* __restrict__ edge_bias,
                         __nv_bfloat16* __restrict__ oh,
                         __nv_bfloat16* __restrict__ ol, int N)
{
    int node = blockIdx.x * 4 + (threadIdx.x >> 6);
    if (node >= N) return;
    int c = (threadIdx.x & 63) * 4;
    int beg = g_off[node], end = g_off[node + 1];
    float4 acc = *(const float4*)(edge_bias + c);
    int i = beg;
    for (; i + 2 <= end; i += 2) {                // 2-way ILP
        int s0 = g_eidx[i], s1 = g_eidx[i + 1];
        float4 v0 = *(const float4*)(nw + (size_t)s0 * H + c);
        float4 v1 = *(const float4*)(nw + (size_t)s1 * H + c);
        acc.x += v0.x; acc.y += v0.y; acc.z += v0.z; acc.w += v0.w;
        acc.x += v1.x; acc.y += v1.y; acc.z += v1.z; acc.w += v1.w;
    }
    if (i < end) {
        int s0 = g_eidx[i];
        float4 v0 = *(const float4*)(nw + (size_t)s0 * H + c);
        acc.x += v0.x; acc.y += v0.y; acc.z += v0.z; acc.w += v0.w;
    }
    __nv_bfloat162 h0 = __floats2bfloat162_rn(acc.x, acc.y);
    __nv_bfloat162 h1 = __floats2bfloat162_rn(acc.z, acc.w);
    __nv_bfloat162 l0 = __floats2bfloat162_rn(acc.x - __low2float(h0), acc.y - __high2float(h0));
    __nv_bfloat162 l1 = __floats2bfloat162_rn(acc.z - __low2float(h1), acc.w - __high2float(h1));
    size_t o = (size_t)node * H + c;
    *(__nv_bfloat162*)(oh + o)     = h0;
    *(__nv_bfloat162*)(oh + o + 2) = h1;
    *(__nv_bfloat162*)(ol + o)     = l0;
    *(__nv_bfloat162*)(ol + o + 2) = l1;
}

// ---------------- fp32 → bf16 hi/lo split (x) ----------------
__global__ void k_split(const float* __restrict__ src,
                        __nv_bfloat16* __restrict__ hi,
                        __nv_bfloat16* __restrict__ lo, int n4)
{
    int idx = blockIdx.x * blockDim.x + threadIdx.x;
    if (idx >= n4) return;
    float4 v = ((const float4*)src)[idx];
    __nv_bfloat162 h0 = __floats2bfloat162_rn(v.x, v.y);
    __nv_bfloat162 h1 = __floats2bfloat162_rn(v.z, v.w);
    __nv_bfloat162 l0 = __floats2bfloat162_rn(v.x - __low2float(h0), v.y - __high2float(h0));
    __nv_bfloat162 l1 = __floats2bfloat162_rn(v.z - __low2float(h1), v.w - __high2float(h1));
    ((__nv_bfloat162*)hi)[idx * 2]     = h0;
    ((__nv_bfloat162*)hi)[idx * 2 + 1] = h1;
    ((__nv_bfloat162*)lo)[idx * 2]     = l0;
    ((__nv_bfloat162*)lo)[idx * 2 + 1] = l1;
}

// ================= bf16 split-3 tensor GEMM =================
#define TK 32
#define PITCH 80
#define TILE_B (128 * PITCH)
#define STAGE_B (4 * TILE_B)
#define GEMM_SMEM (2 * STAGE_B)

__global__ void __launch_bounds__(256)
k_gemm_bf(const __nv_bfloat16* __restrict__ Ah0, const __nv_bfloat16* __restrict__ Al0, int K0,
          const __nv_bfloat16* __restrict__ Ah1, const __nv_bfloat16* __restrict__ Al1, int K1,
          const __nv_bfloat16* __restrict__ Bh0, const __nv_bfloat16* __restrict__ Bl0,
          const __nv_bfloat16* __restrict__ Bh1, const __nv_bfloat16* __restrict__ Bl1,
          float* __restrict__ outF,
          __nv_bfloat16* __restrict__ outH, __nv_bfloat16* __restrict__ outL,
          int M, const float* __restrict__ bias)
{
    extern __shared__ char smem_[];
    const uint32_t sbase = s2u(smem_);
    const int tid  = threadIdx.x;
    const int lane = tid & 31;
    const int wid  = tid >> 5;
    const int wm   = wid & 1;
    const int wn   = wid >> 1;
    const int gr   = lane >> 2;
    const int tg   = lane & 3;
    const int mBase = blockIdx.x * 128;
    const int nBase = blockIdx.y * 128;

    const int srow = tid >> 1;
    const int sq0  = (tid & 1) * 2;

    const int T = (K0 + K1) / TK;

    auto issue = [&](int t) {
        const int kc0 = t * TK;
        const __nv_bfloat16 *Ah, *Al, *Bh, *Bl;
        int lda, ldb, kc;
        if (kc0 < K0) { Ah = Ah0; Al = Al0; Bh = Bh0; Bl = Bl0; lda = K0; ldb = K0; kc = kc0; }
        else          { Ah = Ah1; Al = Al1; Bh = Bh1; Bl = Bl1; lda = K1; ldb = K1; kc = kc0 - K0; }
        uint32_t st = sbase + (t & 1) * STAGE_B;
        int arow = mBase + srow; if (arow >= M) arow = M - 1;
        const size_t aoff = (size_t)arow * lda + kc + sq0 * 8;
        const size_t boff = (size_t)(nBase + srow) * ldb + kc + sq0 * 8;
        uint32_t d = st + srow * PITCH + sq0 * 16;
        CPA16(d,                   Ah + aoff);
        CPA16(d + 16,              Ah + aoff + 8);
        CPA16(d + TILE_B,          Al + aoff);
        CPA16(d + TILE_B + 16,     Al + aoff + 8);
        CPA16(d + 2 * TILE_B,      Bh + boff);
        CPA16(d + 2 * TILE_B + 16, Bh + boff + 8);
        CPA16(d + 3 * TILE_B,      Bl + boff);
        CPA16(d + 3 * TILE_B + 16, Bl + boff + 8);
        CPA_COMMIT();
    };

    float acc[4][4][4];
    #pragma unroll
    for (int i = 0; i < 4; i++)
        #pragma unroll
        for (int j = 0; j < 4; j++)
            #pragma unroll
            for (int q = 0; q < 4; q++) acc[i][j][q] = 0.f;

    const int a_row = (lane & 7) + ((lane >> 3) & 1) * 8;
    const int a_kb  = (lane >> 4) * 16;
    const int b_row = (lane & 7) + ((lane >> 4) & 1) * 8;
    const int b_kb  = ((lane >> 3) & 1) * 16;

    issue(0);

    for (int t = 0; t < T; t++) {
        if (t + 1 < T) { issue(t + 1); CPA_WAIT1(); }
        else           { CPA_WAIT0(); }
        __syncthreads();

        uint32_t st = sbase + (t & 1) * STAGE_B;
        uint32_t sAh = st, sAl = st + TILE_B, sBh = st + 2 * TILE_B, sBl = st + 3 * TILE_B;

        #pragma unroll
        for (int s = 0; s < 2; s++) {
            const int skb = s * 32;
            uint32_t bH[4][2], bL[4][2];
            #pragma unroll
            for (int p = 0; p < 2; p++) {
                uint32_t ba = (wn * 32 + p * 16 + b_row) * PITCH + skb + b_kb;
                LDSM4(bH[2 * p][0], bH[2 * p][1], bH[2 * p + 1][0], bH[2 * p + 1][1], sBh + ba);
                LDSM4(bL[2 * p][0], bL[2 * p][1], bL[2 * p + 1][0], bL[2 * p + 1][1], sBl + ba);
            }
            #pragma unroll
            for (int mt = 0; mt < 4; mt++) {
                uint32_t aH[4], aL[4];
                uint32_t aa = (wm * 64 + mt * 16 + a_row) * PITCH + skb + a_kb;
                LDSM4(aH[0], aH[1], aH[2], aH[3], sAh + aa);
                LDSM4(aL[0], aL[1], aL[2], aL[3], sAl + aa);
                #pragma unroll
                for (int nt = 0; nt < 4; nt++) {
                    MMA16816(acc[mt][nt], aH, bH[nt]);
                    MMA16816(acc[mt][nt], aH, bL[nt]);
                    MMA16816(acc[mt][nt], aL, bH[nt]);
                }
            }
        }
        __syncthreads();
    }

    #pragma unroll
    for (int nt = 0; nt < 4; nt++) {
        int col = nBase + wn * 32 + nt * 8 + tg * 2;
        float b0 = bias[col], b1 = bias[col + 1];
        #pragma unroll
        for (int mt = 0; mt < 4; mt++) {
            int r0 = mBase + wm * 64 + mt * 16 + gr;
            int r1 = r0 + 8;
            float v0 = acc[mt][nt][0] + b0;
            float v1 = acc[mt][nt][1] + b1;
            float v2 = acc[mt][nt][2] + b0;
            float v3 = acc[mt][nt][3] + b1;
            v0 = (v0 >= 0.f) ? v0 : SLOPE * v0;
            v1 = (v1 >= 0.f) ? v1 : SLOPE * v1;
            v2 = (v2 >= 0.f) ? v2 : SLOPE * v2;
            v3 = (v3 >= 0.f) ? v3 : SLOPE * v3;
            if (outF) {
                if (r0 < M) *(float2*)(outF + (size_t)r0 * H + col) = make_float2(v0, v1);
                if (r1 < M) *(float2*)(outF + (size_t)r1 * H + col) = make_float2(v2, v3);
            } else {
                __nv_bfloat162 h0 = __floats2bfloat162_rn(v0, v1);
                __nv_bfloat162 h1 = __floats2bfloat162_rn(v2, v3);
                __nv_bfloat162 l0 = __floats2bfloat162_rn(v0 - __low2float(h0), v1 - __high2float(h0));
                __nv_bfloat162 l1 = __floats2bfloat162_rn(v2 - __low2float(h1), v3 - __high2float(h1));
                if (r0 < M) {
                    *(__nv_bfloat162*)(outH + (size_t)r0 * H + col) = h0;
                    *(__nv_bfloat162*)(outL + (size_t)r0 * H + col) = l0;
                }
                if (r1 < M) {
                    *(__nv_bfloat162*)(outH + (size_t)r1 * H + col) = h1;
                    *(__nv_bfloat162*)(outL + (size_t)r1 * H + col) = l1;
                }
            }
        }
    }
}

// ---------------- launch ----------------
extern "C" void kernel_launch(void* const* d_in, const int* in_sizes, int n_in,
                              void* d_out, int out_size)
{
    const float* x          = (const float*)d_in[0];
    const int*   edge_index = (const int*)  d_in[1];
    const float* w          = (const float*)d_in[2];
    const float* node_w     = (const float*)d_in[3];
    const float* edge_bias  = (const float*)d_in[4];
    const float* le_aw      = (const float*)d_in[5];
    const float* le_ab      = (const float*)d_in[6];
    const float* le_weight  = (const float*)d_in[7];
    const float* le_bias    = (const float*)d_in[8];
    const float* cat1_w     = (const float*)d_in[10];
    const float* cat1_b     = (const float*)d_in[11];
    const float* cat2_w     = (const float*)d_in[12];
    const float* cat2_b     = (const float*)d_in[13];
    const float* nm_w       = (const float*)d_in[14];
    const float* nm_b       = (const float*)d_in[15];
    const float* f1_aw      = (const float*)d_in[16];
    const float* f1_ab      = (const float*)d_in[17];
    const float* f1_weight  = (const float*)d_in[18];
    const float* f1_bias    = (const float*)d_in[19];
    const float* f2_aw      = (const float*)d_in[21];
    const float* f2_ab      = (const float*)d_in[22];
    const float* f2_weight  = (const float*)d_in[23];
    const float* f2_bias    = (const float*)d_in[24];

    int N = in_sizes[3] / H;
    int E = in_sizes[1] / 2;

    float *b2v;
    __nv_bfloat16 *ah, *al, *bh, *bl, *xh, *xl, *wh, *wl, *c1h, *c1l, *nmh, *nml;
    cudaGetSymbolAddress((void**)&b2v, g_b2);
    cudaGetSymbolAddress((void**)&ah,  g_ah);
    cudaGetSymbolAddress((void**)&al,  g_al);
    cudaGetSymbolAddress((void**)&bh,  g_bh);
    cudaGetSymbolAddress((void**)&bl,  g_bl);
    cudaGetSymbolAddress((void**)&xh,  g_xh);
    cudaGetSymbolAddress((void**)&xl,  g_xl);
    cudaGetSymbolAddress((void**)&wh,  g_Wh);
    cudaGetSymbolAddress((void**)&wl,  g_Wl);
    cudaGetSymbolAddress((void**)&c1h, g_C1h);
    cudaGetSymbolAddress((void**)&c1l, g_C1l);
    cudaGetSymbolAddress((void**)&nmh, g_NMh);
    cudaGetSymbolAddress((void**)&nml, g_NMl);

    static int attr_done = 0;
    if (!attr_done) {
        cudaFuncSetAttribute(k_gemm_bf, cudaFuncAttributeMaxDynamicSharedMemorySize, GEMM_SMEM);
        attr_done = 1;
    }

    // weight prep
    k_styles   <<<dim3(2 * H * RANKV / 8, 3), 256>>>(le_aw, le_ab, f1_aw, f1_ab, f2_aw, f2_ab, w);
    k_modweight<<<dim3(H, 3), 256>>>(le_weight, f1_weight, f2_weight);
    k_prep_c1  <<<H * H / 256, 256>>>(cat1_w);
    k_prep_nm  <<<H, INDIM>>>(nm_w, cat2_w);
    k_prep_b2  <<<1, H>>>(cat1_b, cat2_b, nm_b, cat2_w);

    // CSR build + gather aggregation (fused bias + bf16 split)
    k_zero_deg <<<(N + 255) / 256, 256>>>(N);
    k_hist     <<<(E + 255) / 256, 256>>>(edge_index, E);
    k_scan     <<<1, 1024>>>(N);
    k_fill     <<<(E + 255) / 256, 256>>>(edge_index, E);
    k_gather   <<<(N + 3) / 4, 256>>>(node_w, edge_bias, ah, al, N);

    // x split
    k_split    <<<(N * INDIM / 4 + 255) / 256, 256>>>(x, xh, xl, N * INDIM / 4);

    dim3 gg((N + 127) / 128, 2);
    // G1: b = leaky(agg @ W_le^T + le_bias)
    k_gemm_bf<<<gg, 256, GEMM_SMEM>>>(ah, al, H, nullptr, nullptr, 0,
                                      wh + 0 * H * H, wl + 0 * H * H, nullptr, nullptr,
                                      nullptr, bh, bl, N, le_bias);
    // G2: a = leaky(b @ (I+cat1^T) + x @ NM + b2)
    k_gemm_bf<<<gg, 256, GEMM_SMEM>>>(bh, bl, H, xh, xl, INDIM,
                                      c1h, c1l, nmh, nml,
                                      nullptr, ah, al, N, b2v);
    // G3: b = leaky(a @ W_f1^T + f1_bias)
    k_gemm_bf<<<gg, 256, GEMM_SMEM>>>(ah, al, H, nullptr, nullptr, 0,
                                      wh + 1 * H * H, wl + 1 * H * H, nullptr, nullptr,
                                      nullptr, bh, bl, N, f1_bias);
    // G4: out = leaky(b @ W_f2^T + f2_bias)
    k_gemm_bf<<<gg, 256, GEMM_SMEM>>>(bh, bl, H, nullptr, nullptr, 0,
                                      wh + 2 * H * H, wl + 2 * H * H, nullptr, nullptr,
                                      (float*)d_out, nullptr, nullptr, N, f2_bias);
}